// round 1
// baseline (speedup 1.0000x reference)
#include <cuda_runtime.h>
#include <math.h>
#include <cstdint>

#define T_LEN   16384
#define NATOMS  512
#define ALEN    512
#define BATCH   8
#define NBLK    16          // T_LEN / BLKSZ
#define BLKSZ   1024
#define SIGL    1536        // (ALEN-1) zeros + up to ALEN chunk samples + pad
#define N_ITER  32
#define EPS_N   1e-8f

// ---------------- device-global scratch (no allocations allowed) ----------------
__device__ float g_dn[NATOMS * ALEN];                        // normalized dictionary
__device__ float g_fm[(size_t)BATCH * NATOMS * T_LEN];       // correlation feature map (256 MB)
__device__ float g_bmax[BATCH * NATOMS * NBLK];              // per-1024-block max
__device__ int   g_barg[BATCH * NATOMS * NBLK];              // absolute t of block max (first on tie)
__device__ float g_sig[BATCH * SIGL];                        // zero-padded scaled chunk for delta corr
__device__ float g_selv[BATCH];
__device__ int   g_seln[BATCH];
__device__ int   g_selt[BATCH];

// ---------------- dictionary normalization ----------------
__global__ void k_norm(const float* __restrict__ d) {
    int n = blockIdx.x;
    int tid = threadIdx.x;
    __shared__ float red[256];
    float s = 0.f;
    for (int a = tid; a < ALEN; a += 256) { float v = d[n * ALEN + a]; s += v * v; }
    red[tid] = s; __syncthreads();
    for (int st = 128; st > 0; st >>= 1) {
        if (tid < st) red[tid] += red[tid + st];
        __syncthreads();
    }
    float inv = 1.0f / (sqrtf(red[0]) + EPS_N);
    for (int a = tid; a < ALEN; a += 256) g_dn[n * ALEN + a] = d[n * ALEN + a] * inv;
}

// ---------------- output init: residual = x, recon = 0 ----------------
__global__ void k_init_out(const float* __restrict__ x, float* __restrict__ out) {
    int i = blockIdx.x * blockDim.x + threadIdx.x;
    int n = BATCH * T_LEN;
    if (i < n) { out[i] = x[i]; out[n + i] = 0.f; }
}

// ---------------- correlation GEMM ----------------
// out[n, s] = sum_a sig[s + a] * dn[n, a]
// !DELTA: sig = x[b] (len T_LEN), writes fm[b][n][t0+s]
//  DELTA: sig = g_sig[b] (len SIGL), subtracts from fm[b][n][off_b + s], off_b = tsel_b - 511
// Block tile 128(n) x 128(s), micro-tile 8x8, BK = 8.
template<bool DELTA>
__global__ __launch_bounds__(256) void k_conv(const float* __restrict__ x) {
    const int b  = blockIdx.z;
    const int n0 = blockIdx.y * 128;
    const int t0 = blockIdx.x * 128;
    const int tid = threadIdx.x;
    const int tn = tid >> 4;   // 0..15 -> n sub-tile
    const int tt = tid & 15;   // 0..15 -> t sub-tile

    const float* sig;
    int siglen, off;
    if (DELTA) {
        off = g_selt[b] - (ALEN - 1);
        sig = g_sig + b * SIGL;
        siglen = SIGL;
    } else {
        off = 0;
        sig = x + b * T_LEN;
        siglen = T_LEN;
    }

    __shared__ __align__(16) float sdn[8][136];   // transposed dn tile [ka][n], padded
    __shared__ __align__(16) float ssg[144];      // sliding signal window (136 used)

    float acc[8][8];
    #pragma unroll
    for (int i = 0; i < 8; i++)
        #pragma unroll
        for (int j = 0; j < 8; j++) acc[i][j] = 0.f;

    for (int a0 = 0; a0 < ALEN; a0 += 8) {
        // load dn tile (128 n x 8 a), transposed into smem
        {
            int nl = tid >> 1;
            int al = (tid & 1) * 4;
            float4 v = *reinterpret_cast<const float4*>(&g_dn[(n0 + nl) * ALEN + a0 + al]);
            sdn[al + 0][nl] = v.x;
            sdn[al + 1][nl] = v.y;
            sdn[al + 2][nl] = v.z;
            sdn[al + 3][nl] = v.w;
        }
        // load signal window: indices [t0+a0, t0+a0+136)
        if (tid < 136) {
            int gi = t0 + a0 + tid;
            ssg[tid] = (gi < siglen) ? sig[gi] : 0.f;
        }
        __syncthreads();

        // register-cache this thread's signal span: ssg[tt*8 .. tt*8+15]
        float sb[16];
        {
            const float4* p = reinterpret_cast<const float4*>(&ssg[tt * 8]);
            float4 v0 = p[0], v1 = p[1], v2 = p[2], v3 = p[3];
            sb[0]=v0.x;  sb[1]=v0.y;  sb[2]=v0.z;  sb[3]=v0.w;
            sb[4]=v1.x;  sb[5]=v1.y;  sb[6]=v1.z;  sb[7]=v1.w;
            sb[8]=v2.x;  sb[9]=v2.y;  sb[10]=v2.z; sb[11]=v2.w;
            sb[12]=v3.x; sb[13]=v3.y; sb[14]=v3.z; sb[15]=v3.w;
        }
        #pragma unroll
        for (int ka = 0; ka < 8; ka++) {
            float rn[8];
            float4 u0 = *reinterpret_cast<const float4*>(&sdn[ka][tn * 8]);
            float4 u1 = *reinterpret_cast<const float4*>(&sdn[ka][tn * 8 + 4]);
            rn[0]=u0.x; rn[1]=u0.y; rn[2]=u0.z; rn[3]=u0.w;
            rn[4]=u1.x; rn[5]=u1.y; rn[6]=u1.z; rn[7]=u1.w;
            #pragma unroll
            for (int i = 0; i < 8; i++)
                #pragma unroll
                for (int j = 0; j < 8; j++)
                    acc[i][j] = fmaf(rn[i], sb[ka + j], acc[i][j]);
        }
        __syncthreads();
    }

    if (!DELTA) {
        #pragma unroll
        for (int i = 0; i < 8; i++) {
            int n = n0 + tn * 8 + i;
            float* dst = &g_fm[((size_t)(b * NATOMS + n)) * T_LEN + t0 + tt * 8];
            float4 w0 = make_float4(acc[i][0], acc[i][1], acc[i][2], acc[i][3]);
            float4 w1 = make_float4(acc[i][4], acc[i][5], acc[i][6], acc[i][7]);
            *reinterpret_cast<float4*>(dst)     = w0;
            *reinterpret_cast<float4*>(dst + 4) = w1;
        }
    } else {
        #pragma unroll
        for (int i = 0; i < 8; i++) {
            int n = n0 + tn * 8 + i;
            float* row = &g_fm[((size_t)(b * NATOMS + n)) * T_LEN];
            #pragma unroll
            for (int j = 0; j < 8; j++) {
                int t = off + t0 + tt * 8 + j;
                if (t >= 0 && t < T_LEN) row[t] -= acc[i][j];
            }
        }
    }
}

// ---------------- block-max maintenance ----------------
__device__ void scan_block_body(int b, int n, int bl) {
    const float* row = &g_fm[((size_t)(b * NATOMS + n)) * T_LEN + bl * BLKSZ];
    int tid = threadIdx.x;
    float4 v = *reinterpret_cast<const float4*>(&row[tid * 4]);
    float bv = v.x; int bt = tid * 4;
    if (v.y > bv) { bv = v.y; bt = tid * 4 + 1; }
    if (v.z > bv) { bv = v.z; bt = tid * 4 + 2; }
    if (v.w > bv) { bv = v.w; bt = tid * 4 + 3; }
    __shared__ float sv[256];
    __shared__ int   st[256];
    sv[tid] = bv; st[tid] = bt;
    __syncthreads();
    for (int s = 128; s > 0; s >>= 1) {
        if (tid < s) {
            if (sv[tid + s] > sv[tid] || (sv[tid + s] == sv[tid] && st[tid + s] < st[tid])) {
                sv[tid] = sv[tid + s]; st[tid] = st[tid + s];
            }
        }
        __syncthreads();
    }
    if (tid == 0) {
        int idx = (b * NATOMS + n) * NBLK + bl;
        g_bmax[idx] = sv[0];
        g_barg[idx] = bl * BLKSZ + st[0];
    }
}

__global__ __launch_bounds__(256) void k_bmax_init() {
    scan_block_body(blockIdx.z, blockIdx.y, blockIdx.x);
}

__global__ __launch_bounds__(256) void k_refresh() {
    int b = blockIdx.z, n = blockIdx.y;
    int t = g_selt[b];
    int lo = max(0, t - (ALEN - 1));
    int hi = min(T_LEN - 1, t + (ALEN - 1));
    int bl0 = lo >> 10, bl1 = hi >> 10;
    if (blockIdx.x == 1 && bl1 == bl0) return;   // uniform per block
    int bl = (blockIdx.x == 0) ? bl0 : bl1;
    scan_block_body(b, n, bl);
}

// ---------------- global argmax (first index on tie, flat n*T + t order) ----------------
__global__ __launch_bounds__(256) void k_select() {
    int b = blockIdx.x;
    int tid = threadIdx.x;
    float bv = -3.402823466e38f;
    int   bf = 0x7FFFFFFF;
    const float* bm = &g_bmax[b * NATOMS * NBLK];
    const int*   ba = &g_barg[b * NATOMS * NBLK];
    for (int idx = tid; idx < NATOMS * NBLK; idx += 256) {
        float v = bm[idx];
        int flat = (idx >> 4) * T_LEN + ba[idx];   // idx/NBLK = atom index
        if (v > bv || (v == bv && flat < bf)) { bv = v; bf = flat; }
    }
    __shared__ float sv[256];
    __shared__ int   sf[256];
    sv[tid] = bv; sf[tid] = bf;
    __syncthreads();
    for (int s = 128; s > 0; s >>= 1) {
        if (tid < s) {
            if (sv[tid + s] > sv[tid] || (sv[tid + s] == sv[tid] && sf[tid + s] < sf[tid])) {
                sv[tid] = sv[tid + s]; sf[tid] = sf[tid + s];
            }
        }
        __syncthreads();
    }
    if (tid == 0) {
        g_selv[b] = sv[0];
        g_seln[b] = sf[0] >> 14;            // T_LEN = 2^14
        g_selt[b] = sf[0] & (T_LEN - 1);
    }
}

// ---------------- apply selection: residual/recon update + build delta signal ----------------
__global__ void k_apply(float* __restrict__ out) {
    int b = blockIdx.x;
    int tid = threadIdx.x;          // 512 threads
    float v = g_selv[b];
    int n = g_seln[b];
    int t = g_selt[b];
    int end = min(t + ALEN, T_LEN - 1);   // reference clips to T-1 (position T-1 never written)
    int L = end - t;                      // may be < ALEN near right edge, >= 0
    float* res = out + (size_t)b * T_LEN;
    float* rec = out + (size_t)(BATCH + b) * T_LEN;
    if (tid < L) {
        float w = v * g_dn[n * ALEN + tid];
        res[t + tid] -= w;
        rec[t + tid] += w;
    }
    // g_sig[u] = v*dn[n][u-511] for u-511 in [0, L), else 0  (length SIGL)
    for (int u = tid; u < SIGL; u += 512) {
        int j = u - (ALEN - 1);
        g_sig[b * SIGL + u] = (j >= 0 && j < L) ? v * g_dn[n * ALEN + j] : 0.f;
    }
}

// ---------------- launch ----------------
extern "C" void kernel_launch(void* const* d_in, const int* in_sizes, int n_in,
                              void* d_out, int out_size) {
    const float* x = (const float*)d_in[0];
    const float* d = (const float*)d_in[1];
    float* out = (float*)d_out;

    k_norm<<<NATOMS, 256>>>(d);
    {
        int n = BATCH * T_LEN;
        k_init_out<<<(n + 255) / 256, 256>>>(x, out);
    }
    // full correlation: fm[b][n][t], grid (t-tiles, n-tiles, batch)
    k_conv<false><<<dim3(T_LEN / 128, NATOMS / 128, BATCH), 256>>>(x);
    k_bmax_init<<<dim3(NBLK, NATOMS, BATCH), 256>>>();

    for (int it = 0; it < N_ITER; it++) {
        k_select<<<BATCH, 256>>>();
        k_apply<<<BATCH, 512>>>(out);
        // delta window: s in [0, 1024) mapping to t = tsel - 511 + s
        k_conv<true><<<dim3(1024 / 128, NATOMS / 128, BATCH), 256>>>(x);
        k_refresh<<<dim3(2, NATOMS, BATCH), 256>>>();
    }
}

// round 2
// speedup vs baseline: 1.0603x; 1.0603x over previous
#include <cuda_runtime.h>
#include <math.h>
#include <cstdint>

#define T_LEN   16384
#define NATOMS  512
#define ALEN    512
#define BATCH   8
#define NBLK    16          // T_LEN / BLKSZ
#define BLKSZ   1024
#define SIGL    1536
#define N_ITER  32
#define EPS_N   1e-8f

// packed fp32x2 FMA: d.lo = a.lo*b.lo + c.lo ; d.hi = a.hi*b.hi + c.hi
#define FMA_F32X2(d, a, b, c) \
    asm("fma.rn.f32x2 %0, %1, %2, %3;" : "=l"(d) : "l"(a), "l"(b), "l"(c))
#define PACK_BCAST_F32X2(out, f) \
    asm("mov.b64 %0, {%1, %1};" : "=l"(out) : "r"(__float_as_uint(f)))
#define UNPACK_F32X2_(lo, hi, v) \
    asm("mov.b64 {%0, %1}, %2;" : "=f"(lo), "=f"(hi) : "l"(v))

// ---------------- device-global scratch ----------------
__device__ float g_dn[NATOMS * ALEN];
__device__ float g_fm[(size_t)BATCH * NATOMS * T_LEN];       // 256 MB
__device__ float g_bmax[BATCH * NATOMS * NBLK];
__device__ int   g_barg[BATCH * NATOMS * NBLK];
__device__ float g_sig[BATCH * SIGL];
__device__ float g_selv[BATCH];
__device__ int   g_seln[BATCH];
__device__ int   g_selt[BATCH];

// ---------------- dictionary normalization ----------------
__global__ void k_norm(const float* __restrict__ d) {
    int n = blockIdx.x;
    int tid = threadIdx.x;
    __shared__ float red[256];
    float s = 0.f;
    for (int a = tid; a < ALEN; a += 256) { float v = d[n * ALEN + a]; s += v * v; }
    red[tid] = s; __syncthreads();
    for (int st = 128; st > 0; st >>= 1) {
        if (tid < st) red[tid] += red[tid + st];
        __syncthreads();
    }
    float inv = 1.0f / (sqrtf(red[0]) + EPS_N);
    for (int a = tid; a < ALEN; a += 256) g_dn[n * ALEN + a] = d[n * ALEN + a] * inv;
}

// ---------------- output init ----------------
__global__ void k_init_out(const float* __restrict__ x, float* __restrict__ out) {
    int i = blockIdx.x * blockDim.x + threadIdx.x;
    int n = BATCH * T_LEN;
    if (i < n) { out[i] = x[i]; out[n + i] = 0.f; }
}

// ---------------- correlation GEMM (packed f32x2) ----------------
// out[n, s] = sum_a sig[s + a] * dn[n, a]
// Block tile 128(n) x 128(t), micro-tile 8x8 per thread, BK = 8.
// Accumulators packed in pairs over n: acc2[i2][j] = (n=2*i2, n=2*i2+1) at t-offset j.
template<bool DELTA>
__global__ __launch_bounds__(256, 2) void k_conv(const float* __restrict__ x) {
    const int b  = blockIdx.z;
    const int n0 = blockIdx.y * 128;
    const int t0 = blockIdx.x * 128;
    const int tid = threadIdx.x;
    const int tn = tid >> 4;   // 0..15
    const int tt = tid & 15;   // 0..15

    const float* sig;
    int siglen, off;
    if (DELTA) {
        off = g_selt[b] - (ALEN - 1);
        sig = g_sig + b * SIGL;
        siglen = SIGL;
    } else {
        off = 0;
        sig = x + b * T_LEN;
        siglen = T_LEN;
    }

    __shared__ __align__(16) float sdn[8][136];   // transposed dn tile [ka][n]
    __shared__ __align__(16) float ssg[144];      // signal window (136 used)

    unsigned long long acc2[4][8];
    #pragma unroll
    for (int i = 0; i < 4; i++)
        #pragma unroll
        for (int j = 0; j < 8; j++) acc2[i][j] = 0ull;

    for (int a0 = 0; a0 < ALEN; a0 += 8) {
        {
            int nl = tid >> 1;
            int al = (tid & 1) * 4;
            float4 v = *reinterpret_cast<const float4*>(&g_dn[(n0 + nl) * ALEN + a0 + al]);
            sdn[al + 0][nl] = v.x;
            sdn[al + 1][nl] = v.y;
            sdn[al + 2][nl] = v.z;
            sdn[al + 3][nl] = v.w;
        }
        if (tid < 136) {
            int gi = t0 + a0 + tid;
            ssg[tid] = (gi < siglen) ? sig[gi] : 0.f;
        }
        __syncthreads();

        // broadcast-pack this thread's signal span: sb2[m] = (s, s)
        unsigned long long sb2[16];
        {
            const float4* p = reinterpret_cast<const float4*>(&ssg[tt * 8]);
            float4 v0 = p[0], v1 = p[1], v2 = p[2], v3 = p[3];
            float tmp[16] = {v0.x,v0.y,v0.z,v0.w, v1.x,v1.y,v1.z,v1.w,
                             v2.x,v2.y,v2.z,v2.w, v3.x,v3.y,v3.z,v3.w};
            #pragma unroll
            for (int m = 0; m < 16; m++) PACK_BCAST_F32X2(sb2[m], tmp[m]);
        }

        #pragma unroll
        for (int ka = 0; ka < 8; ka++) {
            // dn pairs over consecutive n: zero pack cost
            const ulonglong2* q = reinterpret_cast<const ulonglong2*>(&sdn[ka][tn * 8]);
            ulonglong2 q0 = q[0], q1 = q[1];
            unsigned long long rn2[4] = {q0.x, q0.y, q1.x, q1.y};
            #pragma unroll
            for (int j = 0; j < 8; j++)
                #pragma unroll
                for (int i2 = 0; i2 < 4; i2++)
                    FMA_F32X2(acc2[i2][j], rn2[i2], sb2[ka + j], acc2[i2][j]);
        }
        __syncthreads();
    }

    // unpack accumulators
    float accf[8][8];
    #pragma unroll
    for (int i2 = 0; i2 < 4; i2++)
        #pragma unroll
        for (int j = 0; j < 8; j++)
            UNPACK_F32X2_(accf[2 * i2][j], accf[2 * i2 + 1][j], acc2[i2][j]);

    if (!DELTA) {
        #pragma unroll
        for (int i = 0; i < 8; i++) {
            int n = n0 + tn * 8 + i;
            float* dst = &g_fm[((size_t)(b * NATOMS + n)) * T_LEN + t0 + tt * 8];
            float4 w0 = make_float4(accf[i][0], accf[i][1], accf[i][2], accf[i][3]);
            float4 w1 = make_float4(accf[i][4], accf[i][5], accf[i][6], accf[i][7]);
            *reinterpret_cast<float4*>(dst)     = w0;
            *reinterpret_cast<float4*>(dst + 4) = w1;
        }
    } else {
        #pragma unroll
        for (int i = 0; i < 8; i++) {
            int n = n0 + tn * 8 + i;
            float* row = &g_fm[((size_t)(b * NATOMS + n)) * T_LEN];
            #pragma unroll
            for (int j = 0; j < 8; j++) {
                int t = off + t0 + tt * 8 + j;
                if (t >= 0 && t < T_LEN) row[t] -= accf[i][j];
            }
        }
    }
}

// ---------------- block-max maintenance ----------------
__device__ void scan_block_body(int b, int n, int bl) {
    const float* row = &g_fm[((size_t)(b * NATOMS + n)) * T_LEN + bl * BLKSZ];
    int tid = threadIdx.x;
    float4 v = *reinterpret_cast<const float4*>(&row[tid * 4]);
    float bv = v.x; int bt = tid * 4;
    if (v.y > bv) { bv = v.y; bt = tid * 4 + 1; }
    if (v.z > bv) { bv = v.z; bt = tid * 4 + 2; }
    if (v.w > bv) { bv = v.w; bt = tid * 4 + 3; }
    __shared__ float sv[256];
    __shared__ int   st[256];
    sv[tid] = bv; st[tid] = bt;
    __syncthreads();
    for (int s = 128; s > 0; s >>= 1) {
        if (tid < s) {
            if (sv[tid + s] > sv[tid] || (sv[tid + s] == sv[tid] && st[tid + s] < st[tid])) {
                sv[tid] = sv[tid + s]; st[tid] = st[tid + s];
            }
        }
        __syncthreads();
    }
    if (tid == 0) {
        int idx = (b * NATOMS + n) * NBLK + bl;
        g_bmax[idx] = sv[0];
        g_barg[idx] = bl * BLKSZ + st[0];
    }
}

__global__ __launch_bounds__(256) void k_bmax_init() {
    scan_block_body(blockIdx.z, blockIdx.y, blockIdx.x);
}

__global__ __launch_bounds__(256) void k_refresh() {
    int b = blockIdx.z, n = blockIdx.y;
    int t = g_selt[b];
    int lo = max(0, t - (ALEN - 1));
    int hi = min(T_LEN - 1, t + (ALEN - 1));
    int bl0 = lo >> 10, bl1 = hi >> 10;
    if (blockIdx.x == 1 && bl1 == bl0) return;
    int bl = (blockIdx.x == 0) ? bl0 : bl1;
    scan_block_body(b, n, bl);
}

// ---------------- fused select + apply ----------------
// Phase 1: global argmax over block maxima (first flat index on tie).
// Phase 2: residual/recon update + build zero-padded delta signal.
__global__ __launch_bounds__(512) void k_select_apply(float* __restrict__ out) {
    int b = blockIdx.x;
    int tid = threadIdx.x;        // 512 threads
    float bv = -3.402823466e38f;
    int   bf = 0x7FFFFFFF;
    const float* bm = &g_bmax[b * NATOMS * NBLK];
    const int*   ba = &g_barg[b * NATOMS * NBLK];
    for (int idx = tid; idx < NATOMS * NBLK; idx += 512) {
        float v = bm[idx];
        int flat = (idx >> 4) * T_LEN + ba[idx];
        if (v > bv || (v == bv && flat < bf)) { bv = v; bf = flat; }
    }
    __shared__ float sv[512];
    __shared__ int   sf[512];
    sv[tid] = bv; sf[tid] = bf;
    __syncthreads();
    for (int s = 256; s > 0; s >>= 1) {
        if (tid < s) {
            if (sv[tid + s] > sv[tid] || (sv[tid + s] == sv[tid] && sf[tid + s] < sf[tid])) {
                sv[tid] = sv[tid + s]; sf[tid] = sf[tid + s];
            }
        }
        __syncthreads();
    }
    float v = sv[0];
    int n = sf[0] >> 14;             // T_LEN = 2^14
    int t = sf[0] & (T_LEN - 1);
    if (tid == 0) {
        g_selv[b] = v;
        g_seln[b] = n;
        g_selt[b] = t;
    }
    int end = min(t + ALEN, T_LEN - 1);   // ref clips: position T-1 never written
    int L = end - t;
    float* res = out + (size_t)b * T_LEN;
    float* rec = out + (size_t)(BATCH + b) * T_LEN;
    if (tid < L) {
        float w = v * g_dn[n * ALEN + tid];
        res[t + tid] -= w;
        rec[t + tid] += w;
    }
    for (int u = tid; u < SIGL; u += 512) {
        int j = u - (ALEN - 1);
        g_sig[b * SIGL + u] = (j >= 0 && j < L) ? v * g_dn[n * ALEN + j] : 0.f;
    }
}

// ---------------- launch ----------------
extern "C" void kernel_launch(void* const* d_in, const int* in_sizes, int n_in,
                              void* d_out, int out_size) {
    const float* x = (const float*)d_in[0];
    const float* d = (const float*)d_in[1];
    float* out = (float*)d_out;

    k_norm<<<NATOMS, 256>>>(d);
    {
        int n = BATCH * T_LEN;
        k_init_out<<<(n + 255) / 256, 256>>>(x, out);
    }
    k_conv<false><<<dim3(T_LEN / 128, NATOMS / 128, BATCH), 256>>>(x);
    k_bmax_init<<<dim3(NBLK, NATOMS, BATCH), 256>>>();

    for (int it = 0; it < N_ITER; it++) {
        k_select_apply<<<BATCH, 512>>>(out);
        k_conv<true><<<dim3(1024 / 128, NATOMS / 128, BATCH), 256>>>(x);
        k_refresh<<<dim3(2, NATOMS, BATCH), 256>>>();
    }
}

// round 3
// speedup vs baseline: 1.1439x; 1.0788x over previous
#include <cuda_runtime.h>
#include <math.h>
#include <cstdint>

#define T_LEN   16384
#define NATOMS  512
#define ALEN    512
#define BATCH   8
#define NBLK    16
#define BLKSZ   1024
#define SIGL    1536
#define N_ITER  32
#define EPS_N   1e-8f

#define FMA_F32X2(d, a, b, c) \
    asm("fma.rn.f32x2 %0, %1, %2, %3;" : "=l"(d) : "l"(a), "l"(b), "l"(c))
#define PACK_BCAST_F32X2(out, f) \
    asm("mov.b64 %0, {%1, %1};" : "=l"(out) : "r"(__float_as_uint(f)))
#define UNPACK_F32X2_(lo, hi, v) \
    asm("mov.b64 {%0, %1}, %2;" : "=f"(lo), "=f"(hi) : "l"(v))

// ---------------- device-global scratch ----------------
__device__ float g_dn[NATOMS * ALEN];
__device__ float g_fm[(size_t)BATCH * NATOMS * T_LEN];       // 256 MB
__device__ float g_bmax[BATCH * NATOMS * NBLK];
__device__ int   g_barg[BATCH * NATOMS * NBLK];
__device__ float g_sig[BATCH * SIGL];
__device__ float g_selv[BATCH];
__device__ int   g_seln[BATCH];
__device__ int   g_selt[BATCH];

// ---------------- dictionary normalization ----------------
__global__ void k_norm(const float* __restrict__ d) {
    int n = blockIdx.x;
    int tid = threadIdx.x;
    __shared__ float red[256];
    float s = 0.f;
    for (int a = tid; a < ALEN; a += 256) { float v = d[n * ALEN + a]; s += v * v; }
    red[tid] = s; __syncthreads();
    for (int st = 128; st > 0; st >>= 1) {
        if (tid < st) red[tid] += red[tid + st];
        __syncthreads();
    }
    float inv = 1.0f / (sqrtf(red[0]) + EPS_N);
    for (int a = tid; a < ALEN; a += 256) g_dn[n * ALEN + a] = d[n * ALEN + a] * inv;
}

// ---------------- output init ----------------
__global__ void k_init_out(const float* __restrict__ x, float* __restrict__ out) {
    int i = blockIdx.x * blockDim.x + threadIdx.x;
    int n = BATCH * T_LEN;
    if (i < n) { out[i] = x[i]; out[n + i] = 0.f; }
}

// ---------------- correlation GEMM (packed f32x2, sliding signal ring) ----------------
// out[n, s] = sum_a sig[s + a] * dn[n, a]
// Block tile 128(n) x TT(t); thread micro-tile 8(n) x JT(t), JT = TT/16.
// Accumulators packed in n-pairs. DELTA path clamps k-range to the nonzero
// support of the zero-padded delta signal and subtracts into fm.
template<int TT, bool DELTA>
__global__ __launch_bounds__(256, 2) void k_conv(const float* __restrict__ x) {
    constexpr int JT = TT / 16;
    const int b  = blockIdx.z;
    const int n0 = blockIdx.y * 128;
    const int t0 = blockIdx.x * TT;
    const int tid = threadIdx.x;
    const int tn = tid >> 4;
    const int tt = tid & 15;

    const float* sig;
    int siglen, off;
    int a_begin = 0, a_end = ALEN;
    if (DELTA) {
        int tsel = g_selt[b];
        off = tsel - (ALEN - 1);
        sig = g_sig + b * SIGL;
        siglen = SIGL;
        // t-range of this tile in absolute coords; skip if fully outside
        if (off + t0 >= T_LEN || off + t0 + TT - 1 < 0) return;
        int end = min(tsel + ALEN, T_LEN - 1);
        int L = end - tsel;                       // nonzero sig: u in [511, 511+L)
        int a_lo = max(0, (ALEN - 1) - (t0 + TT - 1));
        int a_hi = min(ALEN, (ALEN - 1) + L - t0);  // exclusive
        if (a_lo >= a_hi) return;                   // delta identically zero here
        a_begin = a_lo & ~7;
        a_end   = (a_hi + 7) & ~7;
    } else {
        off = 0;
        sig = x + b * T_LEN;
        siglen = T_LEN;
    }

    __shared__ __align__(16) float sdn[8][136];     // transposed dn tile [ka][n]
    __shared__ __align__(16) float ssg[TT + 16];    // signal window (TT+8 used)

    unsigned long long acc2[4][JT];
    #pragma unroll
    for (int i = 0; i < 4; i++)
        #pragma unroll
        for (int j = 0; j < JT; j++) acc2[i][j] = 0ull;

    for (int a0 = a_begin; a0 < a_end; a0 += 8) {
        {
            int nl = tid >> 1;
            int al = (tid & 1) * 4;
            float4 v = *reinterpret_cast<const float4*>(&g_dn[(n0 + nl) * ALEN + a0 + al]);
            sdn[al + 0][nl] = v.x;
            sdn[al + 1][nl] = v.y;
            sdn[al + 2][nl] = v.z;
            sdn[al + 3][nl] = v.w;
        }
        if (tid < TT + 8) {
            int gi = t0 + a0 + tid;
            ssg[tid] = (gi < siglen) ? sig[gi] : 0.f;
        }
        __syncthreads();

        // sliding ring of JT broadcast-packed signal values
        // invariant before step ka: ring holds indices {ka..ka+JT-1}, index i at slot i%JT
        unsigned long long w2[JT];
        #pragma unroll
        for (int m = 0; m < JT; m++) PACK_BCAST_F32X2(w2[m], ssg[tt * JT + m]);

        #pragma unroll
        for (int ka = 0; ka < 8; ka++) {
            const ulonglong2* q = reinterpret_cast<const ulonglong2*>(&sdn[ka][tn * 8]);
            ulonglong2 q0 = q[0], q1 = q[1];
            unsigned long long rn2[4] = {q0.x, q0.y, q1.x, q1.y};
            #pragma unroll
            for (int j = 0; j < JT; j++) {
                unsigned long long sv = w2[(ka + j) % JT];
                #pragma unroll
                for (int i2 = 0; i2 < 4; i2++)
                    FMA_F32X2(acc2[i2][j], rn2[i2], sv, acc2[i2][j]);
            }
            if (ka < 7) PACK_BCAST_F32X2(w2[ka % JT], ssg[tt * JT + ka + JT]);
        }
        __syncthreads();
    }

    float accf[8][JT];
    #pragma unroll
    for (int i2 = 0; i2 < 4; i2++)
        #pragma unroll
        for (int j = 0; j < JT; j++)
            UNPACK_F32X2_(accf[2 * i2][j], accf[2 * i2 + 1][j], acc2[i2][j]);

    if (!DELTA) {
        #pragma unroll
        for (int i = 0; i < 8; i++) {
            int n = n0 + tn * 8 + i;
            float* dst = &g_fm[((size_t)(b * NATOMS + n)) * T_LEN + t0 + tt * JT];
            #pragma unroll
            for (int j4 = 0; j4 < JT; j4 += 4) {
                float4 w = make_float4(accf[i][j4], accf[i][j4 + 1],
                                       accf[i][j4 + 2], accf[i][j4 + 3]);
                *reinterpret_cast<float4*>(dst + j4) = w;
            }
        }
    } else {
        #pragma unroll
        for (int i = 0; i < 8; i++) {
            int n = n0 + tn * 8 + i;
            float* row = &g_fm[((size_t)(b * NATOMS + n)) * T_LEN];
            #pragma unroll
            for (int j = 0; j < JT; j++) {
                int t = off + t0 + tt * JT + j;
                if (t >= 0 && t < T_LEN) row[t] -= accf[i][j];
            }
        }
    }
}

// ---------------- block-max maintenance ----------------
__device__ void scan_block_body(int b, int n, int bl) {
    const float* row = &g_fm[((size_t)(b * NATOMS + n)) * T_LEN + bl * BLKSZ];
    int tid = threadIdx.x;
    float4 v = *reinterpret_cast<const float4*>(&row[tid * 4]);
    float bv = v.x; int bt = tid * 4;
    if (v.y > bv) { bv = v.y; bt = tid * 4 + 1; }
    if (v.z > bv) { bv = v.z; bt = tid * 4 + 2; }
    if (v.w > bv) { bv = v.w; bt = tid * 4 + 3; }
    __shared__ float sv[256];
    __shared__ int   st[256];
    sv[tid] = bv; st[tid] = bt;
    __syncthreads();
    for (int s = 128; s > 0; s >>= 1) {
        if (tid < s) {
            if (sv[tid + s] > sv[tid] || (sv[tid + s] == sv[tid] && st[tid + s] < st[tid])) {
                sv[tid] = sv[tid + s]; st[tid] = st[tid + s];
            }
        }
        __syncthreads();
    }
    if (tid == 0) {
        int idx = (b * NATOMS + n) * NBLK + bl;
        g_bmax[idx] = sv[0];
        g_barg[idx] = bl * BLKSZ + st[0];
    }
}

__global__ __launch_bounds__(256) void k_bmax_init() {
    scan_block_body(blockIdx.z, blockIdx.y, blockIdx.x);
}

__global__ __launch_bounds__(256) void k_refresh() {
    int b = blockIdx.z, n = blockIdx.y;
    int t = g_selt[b];
    int lo = max(0, t - (ALEN - 1));
    int hi = min(T_LEN - 1, t + (ALEN - 1));
    int bl0 = lo >> 10, bl1 = hi >> 10;
    if (blockIdx.x == 1 && bl1 == bl0) return;
    int bl = (blockIdx.x == 0) ? bl0 : bl1;
    scan_block_body(b, n, bl);
}

// ---------------- fused select + apply ----------------
__global__ __launch_bounds__(512) void k_select_apply(float* __restrict__ out) {
    int b = blockIdx.x;
    int tid = threadIdx.x;
    float bv = -3.402823466e38f;
    int   bf = 0x7FFFFFFF;
    const float* bm = &g_bmax[b * NATOMS * NBLK];
    const int*   ba = &g_barg[b * NATOMS * NBLK];
    for (int idx = tid; idx < NATOMS * NBLK; idx += 512) {
        float v = bm[idx];
        int flat = (idx >> 4) * T_LEN + ba[idx];
        if (v > bv || (v == bv && flat < bf)) { bv = v; bf = flat; }
    }
    __shared__ float sv[512];
    __shared__ int   sf[512];
    sv[tid] = bv; sf[tid] = bf;
    __syncthreads();
    for (int s = 256; s > 0; s >>= 1) {
        if (tid < s) {
            if (sv[tid + s] > sv[tid] || (sv[tid + s] == sv[tid] && sf[tid + s] < sf[tid])) {
                sv[tid] = sv[tid + s]; sf[tid] = sf[tid + s];
            }
        }
        __syncthreads();
    }
    float v = sv[0];
    int n = sf[0] >> 14;
    int t = sf[0] & (T_LEN - 1);
    if (tid == 0) {
        g_selv[b] = v;
        g_seln[b] = n;
        g_selt[b] = t;
    }
    int end = min(t + ALEN, T_LEN - 1);   // ref clips: position T-1 never written
    int L = end - t;
    float* res = out + (size_t)b * T_LEN;
    float* rec = out + (size_t)(BATCH + b) * T_LEN;
    if (tid < L) {
        float w = v * g_dn[n * ALEN + tid];
        res[t + tid] -= w;
        rec[t + tid] += w;
    }
    for (int u = tid; u < SIGL; u += 512) {
        int j = u - (ALEN - 1);
        g_sig[b * SIGL + u] = (j >= 0 && j < L) ? v * g_dn[n * ALEN + j] : 0.f;
    }
}

// ---------------- launch ----------------
extern "C" void kernel_launch(void* const* d_in, const int* in_sizes, int n_in,
                              void* d_out, int out_size) {
    const float* x = (const float*)d_in[0];
    const float* d = (const float*)d_in[1];
    float* out = (float*)d_out;

    k_norm<<<NATOMS, 256>>>(d);
    {
        int n = BATCH * T_LEN;
        k_init_out<<<(n + 255) / 256, 256>>>(x, out);
    }
    k_conv<128, false><<<dim3(T_LEN / 128, NATOMS / 128, BATCH), 256>>>(x);
    k_bmax_init<<<dim3(NBLK, NATOMS, BATCH), 256>>>();

    for (int it = 0; it < N_ITER; it++) {
        k_select_apply<<<BATCH, 512>>>(out);
        // delta window: 1024 positions starting at tsel-511, 64-wide t tiles
        k_conv<64, true><<<dim3(16, NATOMS / 128, BATCH), 256>>>(x);
        k_refresh<<<dim3(2, NATOMS, BATCH), 256>>>();
    }
}

// round 6
// speedup vs baseline: 1.2352x; 1.0798x over previous
#include <cuda_runtime.h>
#include <math.h>
#include <cstdint>

#define T_LEN   16384
#define NATOMS  512
#define ALEN    512
#define BATCH   8
#define NBLK    16
#define BLKSZ   1024
#define SIGL    1536
#define N_ITER  32
#define EPS_N   1e-8f

#define TM 128                 // atoms per CTA tile
#define TN 128                 // t positions per CTA tile
#define KC 64                  // K chunk
#define NCHUNK (ALEN / KC)     // 8
#define APAD 68                // padded a-stride in smem (bank-conflict-free frags)
#define SWIN 640               // signal window per CTA: TN + ALEN - 1 (+1 pad)
#define SSTR 648               // padded signal split stride
#define SMEM_U32 (2 * TM * APAD + 2 * SSTR)
#define SMEM_BYTES (SMEM_U32 * 4)

// ---------------- device-global scratch ----------------
__device__ float g_dn[NATOMS * ALEN];
__device__ __align__(16) uint32_t g_dtf[2 * NATOMS * ALEN];   // tf32 big/small splits of dn
__device__ float g_fm[(size_t)BATCH * NATOMS * T_LEN];        // 256 MB
__device__ float g_bmax[BATCH * NATOMS * NBLK];
__device__ int   g_barg[BATCH * NATOMS * NBLK];
__device__ float g_sig[BATCH * SIGL];
__device__ float g_selv[BATCH];
__device__ int   g_seln[BATCH];
__device__ int   g_selt[BATCH];

// ---------------- helpers ----------------
__device__ __forceinline__ uint32_t f2tf32(float v) {
    uint32_t r;
    asm("cvt.rna.tf32.f32 %0, %1;" : "=r"(r) : "f"(v));
    return r;
}
// D(16x8) += A(16x8,row) * B(8x8,col)   [tf32 inputs, f32 accum]
__device__ __forceinline__ void mma8(float* c, const uint32_t* a, const uint32_t* b) {
    asm volatile(
        "mma.sync.aligned.m16n8k8.row.col.f32.tf32.tf32.f32 "
        "{%0,%1,%2,%3}, {%4,%5,%6,%7}, {%8,%9}, {%0,%1,%2,%3};"
        : "+f"(c[0]), "+f"(c[1]), "+f"(c[2]), "+f"(c[3])
        : "r"(a[0]), "r"(a[1]), "r"(a[2]), "r"(a[3]), "r"(b[0]), "r"(b[1]));
}

// ---------------- dictionary normalization ----------------
__global__ void k_norm(const float* __restrict__ d) {
    int n = blockIdx.x;
    int tid = threadIdx.x;
    __shared__ float red[256];
    float s = 0.f;
    for (int a = tid; a < ALEN; a += 256) { float v = d[n * ALEN + a]; s += v * v; }
    red[tid] = s; __syncthreads();
    for (int st = 128; st > 0; st >>= 1) {
        if (tid < st) red[tid] += red[tid + st];
        __syncthreads();
    }
    float inv = 1.0f / (sqrtf(red[0]) + EPS_N);
    for (int a = tid; a < ALEN; a += 256) g_dn[n * ALEN + a] = d[n * ALEN + a] * inv;
}

// ---------------- precompute tf32 splits of the dictionary ----------------
__global__ void k_prep() {
    int n = blockIdx.x;
    for (int a = threadIdx.x; a < ALEN; a += 256) {
        float v = g_dn[n * ALEN + a];
        uint32_t big = f2tf32(v);
        float rem = v - __uint_as_float(big);
        uint32_t sml = f2tf32(rem);
        g_dtf[n * ALEN + a] = big;
        g_dtf[NATOMS * ALEN + n * ALEN + a] = sml;
    }
}

// ---------------- output init ----------------
__global__ void k_init_out(const float* __restrict__ x, float* __restrict__ out) {
    int i = blockIdx.x * blockDim.x + threadIdx.x;
    int n = BATCH * T_LEN;
    if (i < n) { out[i] = x[i]; out[n + i] = 0.f; }
}

// ---------------- tensor-core correlation (3xTF32 mma.sync) ----------------
// fm[n, t] = sum_a dn[n,a] * sig[t + a]
// CTA: 128(n) x 128(t), 8 warps as 2(m) x 4(n-col); warp tile 64(n) x 32(t).
template<bool DELTA>
__global__ __launch_bounds__(256, 1) void k_tconv(const float* __restrict__ x) {
    extern __shared__ __align__(16) uint32_t sm[];
    uint32_t* sA = sm;                       // [2][TM][APAD] dict tf32 splits
    uint32_t* sS = sm + 2 * TM * APAD;       // [2][SSTR] signal tf32 splits

    const int b  = blockIdx.z;
    const int n0 = blockIdx.y * TM;
    const int t0 = blockIdx.x * TN;
    const int tid = threadIdx.x;
    const int wid = tid >> 5;
    const int lane = tid & 31;
    const int wm = wid & 1;            // 0..1  (64-row halves)
    const int wn = wid >> 1;           // 0..3  (32-col quarters)
    const int g = lane >> 2;           // 0..7
    const int tig = lane & 3;          // 0..3

    const float* sig;
    int siglen, off;
    unsigned cmask = (1u << NCHUNK) - 1u;
    if (DELTA) {
        int tsel = g_selt[b];
        off = tsel - (ALEN - 1);
        if (off + t0 >= T_LEN || off + t0 + TN - 1 < 0) return;
        int L = min(tsel + ALEN, T_LEN - 1) - tsel;
        if (L <= 0) return;
        sig = g_sig + b * SIGL;
        siglen = SIGL;
        cmask = 0;
        for (int c = 0; c < NCHUNK; c++) {
            int lo = t0 + c * KC;
            int hi = lo + (TN - 1) + (KC - 1);
            if (lo < (ALEN - 1) + L && hi >= (ALEN - 1)) cmask |= 1u << c;
        }
        if (!cmask) return;
    } else {
        off = 0;
        sig = x + (size_t)b * T_LEN;
        siglen = T_LEN;
    }

    // stage tf32 splits of signal window sig[t0 .. t0+639]
    for (int i = tid; i < SWIN; i += 256) {
        int gi = t0 + i;
        float v = (gi < siglen) ? sig[gi] : 0.f;
        uint32_t big = f2tf32(v);
        float rem = v - __uint_as_float(big);
        sS[i] = big;
        sS[SSTR + i] = f2tf32(rem);
    }

    float acc[4][4][4];
    #pragma unroll
    for (int mi = 0; mi < 4; mi++)
        #pragma unroll
        for (int ni = 0; ni < 4; ni++)
            #pragma unroll
            for (int q = 0; q < 4; q++) acc[mi][ni][q] = 0.f;

    for (int c = 0; c < NCHUNK; c++) {
        if (!((cmask >> c) & 1)) continue;
        int a0 = c * KC;
        __syncthreads();     // protects sA reuse (and first-iter sS staging)
        // stage dict chunk: [128 n][64 a] x 2 splits
        for (int e = tid; e < TM * 16; e += 256) {
            int kq = e & 15;
            int n  = e >> 4;
            size_t gi = (size_t)(n0 + n) * ALEN + a0 + kq * 4;
            uint4 vb = *(const uint4*)&g_dtf[gi];
            uint4 vs = *(const uint4*)&g_dtf[NATOMS * ALEN + gi];
            *(uint4*)&sA[n * APAD + kq * 4] = vb;
            *(uint4*)&sA[TM * APAD + n * APAD + kq * 4] = vs;
        }
        __syncthreads();

        #pragma unroll
        for (int kk = 0; kk < KC / 8; kk++) {
            const int col = kk * 8 + tig;
            uint32_t Ab[4][4], As[4][4], Bb[4][2], Bs[4][2];
            #pragma unroll
            for (int mi = 0; mi < 4; mi++) {
                int rm = wm * 64 + mi * 16 + g;
                const uint32_t* p = &sA[rm * APAD + col];
                Ab[mi][0] = p[0];
                Ab[mi][1] = p[8 * APAD];
                Ab[mi][2] = p[4];
                Ab[mi][3] = p[8 * APAD + 4];
                const uint32_t* q = p + TM * APAD;
                As[mi][0] = q[0];
                As[mi][1] = q[8 * APAD];
                As[mi][2] = q[4];
                As[mi][3] = q[8 * APAD + 4];
            }
            #pragma unroll
            for (int ni = 0; ni < 4; ni++) {
                // B Hankel value at (k, n_local): sig[t0 + n_local + a0 + k]
                int idx = wn * 32 + ni * 8 + g + a0 + col;
                Bb[ni][0] = sS[idx];
                Bb[ni][1] = sS[idx + 4];
                Bs[ni][0] = sS[SSTR + idx];
                Bs[ni][1] = sS[SSTR + idx + 4];
            }
            #pragma unroll
            for (int mi = 0; mi < 4; mi++)
                #pragma unroll
                for (int ni = 0; ni < 4; ni++) {
                    mma8(acc[mi][ni], As[mi], Bb[ni]);
                    mma8(acc[mi][ni], Ab[mi], Bs[ni]);
                    mma8(acc[mi][ni], Ab[mi], Bb[ni]);
                }
        }
    }

    // epilogue
    #pragma unroll
    for (int mi = 0; mi < 4; mi++) {
        int n1 = n0 + wm * 64 + mi * 16 + g;
        float* row1 = g_fm + ((size_t)(b * NATOMS + n1)) * T_LEN;
        float* row2 = row1 + 8 * (size_t)T_LEN;
        #pragma unroll
        for (int ni = 0; ni < 4; ni++) {
            int tc = t0 + wn * 32 + ni * 8 + tig * 2;
            if (!DELTA) {
                *(float2*)(row1 + tc) = make_float2(acc[mi][ni][0], acc[mi][ni][1]);
                *(float2*)(row2 + tc) = make_float2(acc[mi][ni][2], acc[mi][ni][3]);
            } else {
                int t = off + tc;
                if (t >= 0 && t < T_LEN)         row1[t]     -= acc[mi][ni][0];
                if (t + 1 >= 0 && t + 1 < T_LEN) row1[t + 1] -= acc[mi][ni][1];
                if (t >= 0 && t < T_LEN)         row2[t]     -= acc[mi][ni][2];
                if (t + 1 >= 0 && t + 1 < T_LEN) row2[t + 1] -= acc[mi][ni][3];
            }
        }
    }
}

// ---------------- block-max maintenance ----------------
__device__ void scan_block_body(int b, int n, int bl) {
    const float* row = &g_fm[((size_t)(b * NATOMS + n)) * T_LEN + bl * BLKSZ];
    int tid = threadIdx.x;
    float4 v = *reinterpret_cast<const float4*>(&row[tid * 4]);
    float bv = v.x; int bt = tid * 4;
    if (v.y > bv) { bv = v.y; bt = tid * 4 + 1; }
    if (v.z > bv) { bv = v.z; bt = tid * 4 + 2; }
    if (v.w > bv) { bv = v.w; bt = tid * 4 + 3; }
    __shared__ float sv[256];
    __shared__ int   st[256];
    sv[tid] = bv; st[tid] = bt;
    __syncthreads();
    for (int s = 128; s > 0; s >>= 1) {
        if (tid < s) {
            if (sv[tid + s] > sv[tid] || (sv[tid + s] == sv[tid] && st[tid + s] < st[tid])) {
                sv[tid] = sv[tid + s]; st[tid] = st[tid + s];
            }
        }
        __syncthreads();
    }
    if (tid == 0) {
        int idx = (b * NATOMS + n) * NBLK + bl;
        g_bmax[idx] = sv[0];
        g_barg[idx] = bl * BLKSZ + st[0];
    }
}

__global__ __launch_bounds__(256) void k_bmax_init() {
    scan_block_body(blockIdx.z, blockIdx.y, blockIdx.x);
}

__global__ __launch_bounds__(256) void k_refresh() {
    int b = blockIdx.z, n = blockIdx.y;
    int t = g_selt[b];
    int lo = max(0, t - (ALEN - 1));
    int hi = min(T_LEN - 1, t + (ALEN - 1));
    int bl0 = lo >> 10, bl1 = hi >> 10;
    if (blockIdx.x == 1 && bl1 == bl0) return;
    int bl = (blockIdx.x == 0) ? bl0 : bl1;
    scan_block_body(b, n, bl);
}

// ---------------- fused select + apply ----------------
__global__ __launch_bounds__(512) void k_select_apply(float* __restrict__ out) {
    int b = blockIdx.x;
    int tid = threadIdx.x;
    float bv = -3.402823466e38f;
    int   bf = 0x7FFFFFFF;
    const float* bm = &g_bmax[b * NATOMS * NBLK];
    const int*   ba = &g_barg[b * NATOMS * NBLK];
    for (int idx = tid; idx < NATOMS * NBLK; idx += 512) {
        float v = bm[idx];
        int flat = (idx >> 4) * T_LEN + ba[idx];
        if (v > bv || (v == bv && flat < bf)) { bv = v; bf = flat; }
    }
    __shared__ float sv[512];
    __shared__ int   sf[512];
    sv[tid] = bv; sf[tid] = bf;
    __syncthreads();
    for (int s = 256; s > 0; s >>= 1) {
        if (tid < s) {
            if (sv[tid + s] > sv[tid] || (sv[tid + s] == sv[tid] && sf[tid + s] < sf[tid])) {
                sv[tid] = sv[tid + s]; sf[tid] = sf[tid + s];
            }
        }
        __syncthreads();
    }
    float v = sv[0];
    int n = sf[0] >> 14;
    int t = sf[0] & (T_LEN - 1);
    if (tid == 0) {
        g_selv[b] = v;
        g_seln[b] = n;
        g_selt[b] = t;
    }
    int end = min(t + ALEN, T_LEN - 1);   // ref clips: position T-1 never written
    int L = end - t;
    float* res = out + (size_t)b * T_LEN;
    float* rec = out + (size_t)(BATCH + b) * T_LEN;
    if (tid < L) {
        float w = v * g_dn[n * ALEN + tid];
        res[t + tid] -= w;
        rec[t + tid] += w;
    }
    for (int u = tid; u < SIGL; u += 512) {
        int j = u - (ALEN - 1);
        g_sig[b * SIGL + u] = (j >= 0 && j < L) ? v * g_dn[n * ALEN + j] : 0.f;
    }
}

// ---------------- launch ----------------
extern "C" void kernel_launch(void* const* d_in, const int* in_sizes, int n_in,
                              void* d_out, int out_size) {
    const float* x = (const float*)d_in[0];
    const float* d = (const float*)d_in[1];
    float* out = (float*)d_out;

    cudaFuncSetAttribute(k_tconv<false>, cudaFuncAttributeMaxDynamicSharedMemorySize, SMEM_BYTES);
    cudaFuncSetAttribute(k_tconv<true>,  cudaFuncAttributeMaxDynamicSharedMemorySize, SMEM_BYTES);

    k_norm<<<NATOMS, 256>>>(d);
    k_prep<<<NATOMS, 256>>>();
    {
        int n = BATCH * T_LEN;
        k_init_out<<<(n + 255) / 256, 256>>>(x, out);
    }
    k_tconv<false><<<dim3(T_LEN / TN, NATOMS / TM, BATCH), 256, SMEM_BYTES>>>(x);
    k_bmax_init<<<dim3(NBLK, NATOMS, BATCH), 256>>>();

    for (int it = 0; it < N_ITER; it++) {
        k_select_apply<<<BATCH, 512>>>(out);
        k_tconv<true><<<dim3(1024 / TN, NATOMS / TM, BATCH), 256, SMEM_BYTES>>>(x);
        k_refresh<<<dim3(2, NATOMS, BATCH), 256>>>();
    }
}